// round 12
// baseline (speedup 1.0000x reference)
#include <cuda_runtime.h>
#include <cuda_bf16.h>
#include <math.h>
#include <stdint.h>

// Problem dims
#define Bv 4096
#define Tt 28
#define In 28
#define Hh 512
#define Gg 1536   // 3*H
#define H2 1024   // 2*H

#define BH 2097152      // B*H
#define BG 6291456      // B*3H
#define MT 114688       // B*T

// ---------------- scratch (static device allocations; allowed) ----------------
__device__ float g_gxA[176160768];   // B*T*3H : gx layer0 fwd (interleaved), reused for layer1
__device__ float g_gxB[176160768];   // B*T*3H : gx layer0 bwd (interleaved)
__device__ float g_h[2 * 2097152];   // layer0 fwd/bwd hidden (fp32 state)
__device__ float g_h1[2097152];      // layer1 fwd hidden (fp32 state)
__device__ float g_h1b[2097152];     // layer1 bwd hidden (one step)
__device__ float g_gx1b[6291456];    // layer1 bwd gx at t=T-1 (NATURAL layout)
__device__ float g_z1[1048576];      // B*256 fc1 output
__device__ float g_bi[4608];         // 3 interleaved b_ih copies (l0, l0r, l1)

// bf16 operands. A-side stores hi+lo only; GEMMs synthesize [hi|hi|lo] virtually.
// W-side physically stacked [Wh|Wl|Wh]; GRU weights additionally row-interleaved
// (output rows ordered r_u,z_u,n_u per h-unit) so a 96-wide N tile holds all 3
// gates of 32 h-units -> gate math fuses into the GEMM epilogue.
__device__ __nv_bfloat16 g_xs[14680064];     // x stacked [B*T,128] physical
__device__ __nv_bfloat16 g_ws[17694720];     // weights arena (stacked, some interleaved)
__device__ __nv_bfloat16 g_y0h[117440512];   // y0 hi [B*T,1024]
__device__ __nv_bfloat16 g_y0l[117440512];   // y0 lo [B*T,1024]
__device__ __nv_bfloat16 g_hh[2*2*2097152];  // l0 h hi, [buf][dir][B,512]
__device__ __nv_bfloat16 g_hl[2*2*2097152];  // l0 h lo
__device__ __nv_bfloat16 g_h1h[2*2097152];   // l1 h hi, [buf][B,512]
__device__ __nv_bfloat16 g_h1l[2*2097152];   // l1 h lo
__device__ __nv_bfloat16 g_lasth[4194304];   // concat hi [B,1024]
__device__ __nv_bfloat16 g_lastl[4194304];   // concat lo [B,1024]

// Weight arena offsets (bf16 elements)
#define WS_IH_L0   0          // 1536 x 128   (interleaved rows)
#define WS_IH_L0R  196608
#define WS_HH_L0   393216     // 1536 x 1536  (interleaved rows)
#define WS_HH_L0R  2752512
#define WS_HH_L1   5111808
#define WS_IH_L1   7471104    // 1536 x 3072  (interleaved rows)
#define WS_IH_L1R  12189696   // natural rows
#define WS_FC1     16908288   // 256 x 3072   natural

// ============================================================================
// PTX helpers (baseline sm_80+ features; valid on .target sm_103)
// ============================================================================
__device__ __forceinline__ uint32_t smem_u32(const void* p) {
    uint32_t a;
    asm("{ .reg .u64 t; cvta.to.shared.u64 t, %1; cvt.u32.u64 %0, t; }" : "=r"(a) : "l"(p));
    return a;
}
__device__ __forceinline__ void cp16(uint32_t s, const void* g) {
    asm volatile("cp.async.cg.shared.global [%0], [%1], 16;" :: "r"(s), "l"(g));
}
__device__ __forceinline__ void ldsm4(uint32_t* r, uint32_t a) {
    asm volatile("ldmatrix.sync.aligned.m8n8.x4.shared.b16 {%0,%1,%2,%3}, [%4];"
                 : "=r"(r[0]), "=r"(r[1]), "=r"(r[2]), "=r"(r[3]) : "r"(a));
}
__device__ __forceinline__ void mma16816(float* d, const uint32_t* a, uint32_t b0, uint32_t b1) {
    asm volatile("mma.sync.aligned.m16n8k16.row.col.f32.bf16.bf16.f32 "
                 "{%0,%1,%2,%3}, {%4,%5,%6,%7}, {%8,%9}, {%0,%1,%2,%3};"
                 : "+f"(d[0]), "+f"(d[1]), "+f"(d[2]), "+f"(d[3])
                 : "r"(a[0]), "r"(a[1]), "r"(a[2]), "r"(a[3]), "r"(b0), "r"(b1));
}

__device__ __forceinline__ float sigmoidf_(float x) { return 1.f / (1.f + expf(-x)); }
__device__ __forceinline__ void split_bf16(float v, __nv_bfloat16& h, __nv_bfloat16& l) {
    h = __float2bfloat16(v);
    l = __float2bfloat16(v - __bfloat162float(h));
}

// ============================================================================
// Pipelined bf16 GEMM (input projections / fc1): C = A' @ W'^T + bias
// Virtual-stacked A: seg = k>>kshift; seg<2 -> Ahi[k&mask], seg2 -> Alo.
// 128x128x64 tiles, 3-stage cp.async, swizzled ldmatrix, 8 warps (64x32 each).
// ============================================================================
struct MOp {
    const __nv_bfloat16 *Ahi, *Alo;
    const __nv_bfloat16 *W;
    const float *bias;
    float *C;
    int lda;
    int koff;
};

#define STAGE_B 32768
#define SMEM_SZ (3 * STAGE_B)

__device__ __forceinline__ void prefetch_stage(const MOp& op, uint32_t sb, int c,
                                               int bm, int bn, int ldw,
                                               int kshift, int kmask, int tid)
{
    const int st = c % 3;
    const uint32_t abase = sb + st * STAGE_B;
    const uint32_t wbase = abase + 16384;
    const int kc0 = c * 64;
#pragma unroll
    for (int i = 0; i < 4; i++) {
        int v = tid + i * 256;
        int row = v >> 3, ch = v & 7;
        int kg  = op.koff + kc0 + ch * 8;
        int seg = kg >> kshift;
        int off = kg & kmask;
        const __nv_bfloat16* g = (seg < 2 ? op.Ahi : op.Alo)
                               + (size_t)(bm + row) * op.lda + off;
        cp16(abase + row * 128 + ((ch ^ (row & 7)) << 4), g);
    }
#pragma unroll
    for (int i = 0; i < 4; i++) {
        int v = tid + i * 256;
        int row = v >> 3, ch = v & 7;
        const __nv_bfloat16* g = op.W + (size_t)(bn + row) * ldw + kc0 + ch * 8;
        cp16(wbase + row * 128 + ((ch ^ (row & 7)) << 4), g);
    }
    asm volatile("cp.async.commit_group;");
}

__global__ void __launch_bounds__(256, 2) mma_gemm(MOp op0, MOp op1,
                                                   int ldw, int ldc, int K, int kshift)
{
    extern __shared__ char smem[];
    MOp op = (blockIdx.z == 0) ? op0 : op1;
    const uint32_t sb = smem_u32(smem);
    const int kmask = (kshift >= 30) ? 0x3FFFFFFF : ((1 << kshift) - 1);
    const int tid  = threadIdx.x;
    const int wid  = tid >> 5;
    const int lane = tid & 31;
    const int bm = blockIdx.y * 128;
    const int bn = blockIdx.x * 128;
    const int wm = (wid >> 2) * 64;
    const int wn = (wid & 3) * 32;

    float acc[4][4][4];
#pragma unroll
    for (int i = 0; i < 4; i++)
#pragma unroll
        for (int j = 0; j < 4; j++)
#pragma unroll
            for (int r = 0; r < 4; r++) acc[i][j][r] = 0.f;

    const int nc = K >> 6;

    prefetch_stage(op, sb, 0, bm, bn, ldw, kshift, kmask, tid);
    if (nc > 1) prefetch_stage(op, sb, 1, bm, bn, ldw, kshift, kmask, tid);

    for (int c = 0; c < nc; c++) {
        if (c + 2 < nc) {
            prefetch_stage(op, sb, c + 2, bm, bn, ldw, kshift, kmask, tid);
            asm volatile("cp.async.wait_group 2;");
        } else if (c + 1 < nc) {
            asm volatile("cp.async.wait_group 1;");
        } else {
            asm volatile("cp.async.wait_group 0;");
        }
        __syncthreads();

        const int st = c % 3;
        const uint32_t abase = sb + st * STAGE_B;
        const uint32_t wbase = abase + 16384;

#pragma unroll
        for (int kk = 0; kk < 4; kk++) {
            uint32_t a[4][4], b[2][4];
#pragma unroll
            for (int mf = 0; mf < 4; mf++) {
                int r   = wm + mf * 16 + ((lane >> 3) & 1) * 8 + (lane & 7);
                int cch = kk * 2 + (lane >> 4);
                ldsm4(a[mf], abase + r * 128 + ((cch ^ (r & 7)) << 4));
            }
#pragma unroll
            for (int nf = 0; nf < 2; nf++) {
                int r   = wn + nf * 16 + ((lane >> 4) & 1) * 8 + (lane & 7);
                int cch = kk * 2 + ((lane >> 3) & 1);
                ldsm4(b[nf], wbase + r * 128 + ((cch ^ (r & 7)) << 4));
            }
#pragma unroll
            for (int mf = 0; mf < 4; mf++)
#pragma unroll
                for (int nt = 0; nt < 4; nt++)
                    mma16816(acc[mf][nt], a[mf],
                             b[nt >> 1][(nt & 1) * 2], b[nt >> 1][(nt & 1) * 2 + 1]);
        }
        __syncthreads();
    }

#pragma unroll
    for (int mf = 0; mf < 4; mf++) {
        int row = bm + wm + mf * 16 + (lane >> 2);
#pragma unroll
        for (int nt = 0; nt < 4; nt++) {
            int col = bn + wn + nt * 8 + (lane & 3) * 2;
            float b0 = op.bias[col], b1 = op.bias[col + 1];
            float2 v0 = make_float2(acc[mf][nt][0] + b0, acc[mf][nt][1] + b1);
            float2 v1 = make_float2(acc[mf][nt][2] + b0, acc[mf][nt][3] + b1);
            *(float2*)(op.C + (size_t)row * ldc + col) = v0;
            *(float2*)(op.C + (size_t)(row + 8) * ldc + col) = v1;
        }
    }
}

// ============================================================================
// Gate-fused recurrent step. Tile 128(M) x 96(N = 32 h-units x 3 gates),
// K=1536 virtual [hi|hi|lo]. Epilogue does the full GRU update.
// 8 warps as 4(M) x 2(N), warp tile 32x48. 2 CTAs/SM.
// ============================================================================
struct RStep {
    const __nv_bfloat16 *Ahi, *Alo;  // h hi/lo (natural, ld 512)
    const __nv_bfloat16 *W;          // stacked+interleaved Whh [1536,1536]
    const float *bhh;                // natural [1536]
    const float *gx;                 // interleaved [B,T,1536]
    float *h;                        // [B,512] in/out
    __nv_bfloat16 *hho, *hlo;        // out hi/lo (natural)
    __nv_bfloat16 *y0h, *y0l;        // [B,T,1024] or nullptr
    int t, y0off;
};

#define RS_STAGE 28672               // A 16KB + W 12KB
#define RS_SMEM  (3 * RS_STAGE)      // 86016

__device__ __forceinline__ void rs_prefetch(const RStep& s, uint32_t sb, int c,
                                            int bm, int bn, int tid)
{
    const int st = c % 3;
    const uint32_t abase = sb + st * RS_STAGE;
    const uint32_t wbase = abase + 16384;
    const int kc0 = c * 64;
#pragma unroll
    for (int i = 0; i < 4; i++) {           // A: 128 rows x 8 chunks
        int v = tid + i * 256;
        int row = v >> 3, ch = v & 7;
        int kg  = kc0 + ch * 8;
        int seg = kg >> 9;
        int off = kg & 511;
        const __nv_bfloat16* g = (seg < 2 ? s.Ahi : s.Alo) + (size_t)(bm + row) * 512 + off;
        cp16(abase + row * 128 + ((ch ^ (row & 7)) << 4), g);
    }
#pragma unroll
    for (int i = 0; i < 3; i++) {           // W: 96 rows x 8 chunks
        int v = tid + i * 256;
        int row = v >> 3, ch = v & 7;
        const __nv_bfloat16* g = s.W + (size_t)(bn * 96 + row) * 1536 + kc0 + ch * 8;
        cp16(wbase + row * 128 + ((ch ^ (row & 7)) << 4), g);
    }
    asm volatile("cp.async.commit_group;");
}

__global__ void __launch_bounds__(256, 2) rec_step(RStep s0, RStep s1)
{
    extern __shared__ char smem[];
    RStep s = (blockIdx.z == 0) ? s0 : s1;
    const uint32_t sb = smem_u32(smem);
    const int tid  = threadIdx.x;
    const int wid  = tid >> 5;
    const int lane = tid & 31;
    const int bn = blockIdx.x;          // 0..15 over interleaved N
    const int bm = blockIdx.y * 128;
    const int wm = (wid >> 1) * 32;     // 4 warp rows
    const int wn = (wid & 1) * 48;      // 2 warp cols

    float acc[2][6][4];
#pragma unroll
    for (int i = 0; i < 2; i++)
#pragma unroll
        for (int j = 0; j < 6; j++)
#pragma unroll
            for (int r = 0; r < 4; r++) acc[i][j][r] = 0.f;

    const int nc = 24;   // K=1536 / 64

    rs_prefetch(s, sb, 0, bm, bn, tid);
    rs_prefetch(s, sb, 1, bm, bn, tid);

    for (int c = 0; c < nc; c++) {
        if (c + 2 < nc) {
            rs_prefetch(s, sb, c + 2, bm, bn, tid);
            asm volatile("cp.async.wait_group 2;");
        } else if (c + 1 < nc) {
            asm volatile("cp.async.wait_group 1;");
        } else {
            asm volatile("cp.async.wait_group 0;");
        }
        __syncthreads();

        const int st = c % 3;
        const uint32_t abase = sb + st * RS_STAGE;
        const uint32_t wbase = abase + 16384;

#pragma unroll
        for (int kk = 0; kk < 4; kk++) {
            uint32_t a[2][4], b[3][4];
#pragma unroll
            for (int mf = 0; mf < 2; mf++) {
                int r   = wm + mf * 16 + ((lane >> 3) & 1) * 8 + (lane & 7);
                int cch = kk * 2 + (lane >> 4);
                ldsm4(a[mf], abase + r * 128 + ((cch ^ (r & 7)) << 4));
            }
#pragma unroll
            for (int nf = 0; nf < 3; nf++) {
                int r   = wn + nf * 16 + ((lane >> 4) & 1) * 8 + (lane & 7);
                int cch = kk * 2 + ((lane >> 3) & 1);
                ldsm4(b[nf], wbase + r * 128 + ((cch ^ (r & 7)) << 4));
            }
#pragma unroll
            for (int mf = 0; mf < 2; mf++)
#pragma unroll
                for (int nt = 0; nt < 6; nt++)
                    mma16816(acc[mf][nt], a[mf],
                             b[nt >> 1][(nt & 1) * 2], b[nt >> 1][(nt & 1) * 2 + 1]);
        }
        __syncthreads();
    }

    // stage acc tile to smem (pitch 100 floats to avoid bank conflicts)
    float* sg = (float*)smem;
#pragma unroll
    for (int mf = 0; mf < 2; mf++) {
        int row0 = wm + mf * 16 + (lane >> 2);
#pragma unroll
        for (int nt = 0; nt < 6; nt++) {
            int col = wn + nt * 8 + (lane & 3) * 2;
            sg[row0 * 100 + col]           = acc[mf][nt][0];
            sg[row0 * 100 + col + 1]       = acc[mf][nt][1];
            sg[(row0 + 8) * 100 + col]     = acc[mf][nt][2];
            sg[(row0 + 8) * 100 + col + 1] = acc[mf][nt][3];
        }
    }
    __syncthreads();

    // fused GRU gate: 128 rows x 32 h-units
    for (int idx = tid; idx < 4096; idx += 256) {
        const int row = idx >> 5;
        const int u   = idx & 31;
        const int brow = bm + row;
        const int jg   = bn * 32 + u;

        float ar = sg[row * 100 + 3 * u];
        float az = sg[row * 100 + 3 * u + 1];
        float an = sg[row * 100 + 3 * u + 2];

        const float* gxr = s.gx + ((size_t)brow * Tt + s.t) * Gg + bn * 96;
        float r = sigmoidf_(gxr[3 * u]     + ar + s.bhh[jg]);
        float z = sigmoidf_(gxr[3 * u + 1] + az + s.bhh[512 + jg]);
        float n = tanhf(gxr[3 * u + 2] + r * (an + s.bhh[1024 + jg]));

        const size_t hidx = (size_t)brow * 512 + jg;
        float hn = (1.f - z) * n + z * s.h[hidx];
        s.h[hidx] = hn;

        __nv_bfloat16 hh, hl;
        split_bf16(hn, hh, hl);
        s.hho[hidx] = hh;
        s.hlo[hidx] = hl;
        if (s.y0h) {
            const size_t yi = ((size_t)brow * Tt + s.t) * 1024 + s.y0off + jg;
            s.y0h[yi] = hh;
            s.y0l[yi] = hl;
        }
    }
}

// ============================================================================
// init: zero state + build interleaved b_ih copies, one launch
// ============================================================================
#define ZF  (3 * BH)              // g_h (2BH) + g_h1 (BH)
#define ZBI (ZF + 4608)           // bias region
#define ZB  (6 * BH)              // bf16 zero region
#define ZTOT (ZBI + ZB)

__global__ void zero_all(const float* bihA, const float* bihB, const float* bih1)
{
    long long i = (long long)blockIdx.x * blockDim.x + threadIdx.x;
    if (i >= ZTOT) return;
    if (i < ZF) {
        if (i < 2 * BH) g_h[i] = 0.f;
        else            g_h1[i - 2 * BH] = 0.f;
    } else if (i < ZBI) {
        int k = (int)(i - ZF);
        int which = k / 1536, idx = k - which * 1536;
        int g = idx % 3, u = idx / 3;
        const float* src = (which == 0) ? bihA : (which == 1) ? bihB : bih1;
        g_bi[k] = src[g * 512 + u];
    } else {
        long long k = i - ZBI;
        __nv_bfloat16 z = __float2bfloat16(0.f);
        if (k < 2 * BH)      g_hh[k] = z;
        else if (k < 4 * BH) g_hl[k - 2 * BH] = z;
        else if (k < 5 * BH) g_h1h[k - 4 * BH] = z;
        else                 g_h1l[k - 5 * BH] = z;
    }
}

// ============================================================================
// conversion: hi/lo stacking + optional row interleave, one launch
// ============================================================================
struct CvJobs {
    const float* src[9];
    __nv_bfloat16* dst[9];
    int off[10];
    int K[9], Kp[9], modes[9], total[9], ilv[9];
};

__global__ void convert_all(CvJobs jobs)
{
    int bid = blockIdx.x;
    int ji = 0;
#pragma unroll
    for (int t = 1; t < 9; t++) ji += (bid >= jobs.off[t]);
    int i = (bid - jobs.off[ji]) * 256 + threadIdx.x;
    if (i >= jobs.total[ji]) return;
    const float* src = jobs.src[ji];
    int K = jobs.K[ji], Kp = jobs.Kp[ji], modes = jobs.modes[ji];

    int Kt  = (Kp == 32) ? 128 : (Kp == 512 ? 1536 : 3072);
    int row = i / Kt;
    int rem = i - row * Kt;
    int seg = rem / Kp;
    int kk  = rem - seg * Kp;
    int srow = jobs.ilv[ji] ? ((row % 3) * 512 + row / 3) : row;
    int mode = (modes >> (2 * seg)) & 3;
    float v = (mode != 2 && kk < K) ? src[(size_t)srow * K + kk] : 0.f;
    __nv_bfloat16 h = __float2bfloat16(v);
    __nv_bfloat16 o = h;
    if (mode == 1) o = __float2bfloat16(v - __bfloat162float(h));
    jobs.dst[ji][i] = o;
}

// ============================================================================
// remaining small kernels
// ============================================================================
// Layer-1 backward: output at original t=T-1 is the FIRST reversed step (h0=0).
__global__ void gate_l1b_last(const float* __restrict__ bhh)
{
    const int idx = blockIdx.x * blockDim.x + threadIdx.x;
    const int b = idx >> 9;
    const int j = idx & 511;
    const float* gx = g_gx1b + (size_t)b * Gg;
    float r = sigmoidf_(gx[j] + bhh[j]);
    float z = sigmoidf_(gx[Hh + j] + bhh[Hh + j]);
    float n = tanhf(gx[2 * Hh + j] + r * bhh[2 * Hh + j]);
    g_h1b[(size_t)b * Hh + j] = (1.f - z) * n;
}

__global__ void concat_last(void)
{
    const int idx = blockIdx.x * blockDim.x + threadIdx.x;
    const int b = idx >> 10;
    const int j = idx & 1023;
    float v = (j < Hh) ? g_h1[(size_t)b * Hh + j] : g_h1b[(size_t)b * Hh + (j - Hh)];
    __nv_bfloat16 hh, hl;
    split_bf16(v, hh, hl);
    g_lasth[(size_t)b * H2 + j] = hh;
    g_lastl[(size_t)b * H2 + j] = hl;
}

__global__ void head_kernel(const float* __restrict__ gamma, const float* __restrict__ beta,
                            const float* __restrict__ mean, const float* __restrict__ var,
                            const float* __restrict__ fc2w, const float* __restrict__ fc2b,
                            float* __restrict__ out)
{
    const int b = blockIdx.x;
    const int tid = threadIdx.x;
    __shared__ float a[256];
    __shared__ float logits[10];

    float v = g_z1[(size_t)b * 256 + tid];
    v = (v - mean[tid]) * rsqrtf(var[tid] + 1e-5f) * gamma[tid] + beta[tid];
    a[tid] = fmaxf(v, 0.f);
    __syncthreads();

    if (tid < 10) {
        float acc = fc2b[tid];
        const float* wrow = fc2w + tid * 256;
        for (int k = 0; k < 256; k++) acc = fmaf(a[k], wrow[k], acc);
        logits[tid] = acc;
    }
    __syncthreads();

    if (tid == 0) {
        float mx = logits[0];
        for (int i = 1; i < 10; i++) mx = fmaxf(mx, logits[i]);
        float s = 0.f;
        for (int i = 0; i < 10; i++) s += expf(logits[i] - mx);
        float lse = mx + logf(s);
        for (int i = 0; i < 10; i++) out[(size_t)b * 10 + i] = logits[i] - lse;
    }
}

// ============================================================================
// host-side launch
// ============================================================================
extern "C" void kernel_launch(void* const* d_in, const int* in_sizes, int n_in,
                              void* d_out, int out_size)
{
    (void)in_sizes; (void)n_in; (void)out_size;
    const float* x         = (const float*)d_in[0];
    const float* W_ih_l0   = (const float*)d_in[1];
    const float* W_hh_l0   = (const float*)d_in[2];
    const float* b_ih_l0   = (const float*)d_in[3];
    const float* b_hh_l0   = (const float*)d_in[4];
    const float* W_ih_l0r  = (const float*)d_in[5];
    const float* W_hh_l0r  = (const float*)d_in[6];
    const float* b_ih_l0r  = (const float*)d_in[7];
    const float* b_hh_l0r  = (const float*)d_in[8];
    const float* W_ih_l1   = (const float*)d_in[9];
    const float* W_hh_l1   = (const float*)d_in[10];
    const float* b_ih_l1   = (const float*)d_in[11];
    const float* b_hh_l1   = (const float*)d_in[12];
    const float* W_ih_l1r  = (const float*)d_in[13];
    const float* W_hh_l1r  = (const float*)d_in[14];
    const float* b_ih_l1r  = (const float*)d_in[15];
    const float* b_hh_l1r  = (const float*)d_in[16];
    const float* fc1_w     = (const float*)d_in[17];
    const float* fc1_b     = (const float*)d_in[18];
    const float* bn_gamma  = (const float*)d_in[19];
    const float* bn_beta   = (const float*)d_in[20];
    const float* bn_mean   = (const float*)d_in[21];
    const float* bn_var    = (const float*)d_in[22];
    const float* fc2_w     = (const float*)d_in[23];
    const float* fc2_b     = (const float*)d_in[24];
    float* out = (float*)d_out;

    float *p_gxA, *p_gxB, *p_h, *p_h1, *p_gx1b, *p_z1, *p_bi;
    __nv_bfloat16 *p_xs, *p_ws, *p_y0h, *p_y0l, *p_hh, *p_hl, *p_h1h, *p_h1l, *p_lh, *p_ll;
    cudaGetSymbolAddress((void**)&p_gxA,  g_gxA);
    cudaGetSymbolAddress((void**)&p_gxB,  g_gxB);
    cudaGetSymbolAddress((void**)&p_h,    g_h);
    cudaGetSymbolAddress((void**)&p_h1,   g_h1);
    cudaGetSymbolAddress((void**)&p_gx1b, g_gx1b);
    cudaGetSymbolAddress((void**)&p_z1,   g_z1);
    cudaGetSymbolAddress((void**)&p_bi,   g_bi);
    cudaGetSymbolAddress((void**)&p_xs,   g_xs);
    cudaGetSymbolAddress((void**)&p_ws,   g_ws);
    cudaGetSymbolAddress((void**)&p_y0h,  g_y0h);
    cudaGetSymbolAddress((void**)&p_y0l,  g_y0l);
    cudaGetSymbolAddress((void**)&p_hh,   g_hh);
    cudaGetSymbolAddress((void**)&p_hl,   g_hl);
    cudaGetSymbolAddress((void**)&p_h1h,  g_h1h);
    cudaGetSymbolAddress((void**)&p_h1l,  g_h1l);
    cudaGetSymbolAddress((void**)&p_lh,   g_lasth);
    cudaGetSymbolAddress((void**)&p_ll,   g_lastl);

    cudaFuncSetAttribute(mma_gemm, cudaFuncAttributeMaxDynamicSharedMemorySize, SMEM_SZ);
    cudaFuncSetAttribute(rec_step, cudaFuncAttributeMaxDynamicSharedMemorySize, RS_SMEM);

    const int MODES_A4 = 0 | (0 << 2) | (1 << 4) | (2 << 6);  // [hi|hi|lo|0]
    const int MODES_W4 = 0 | (1 << 2) | (0 << 4) | (2 << 6);  // [hi|lo|hi|0]
    const int MODES_W3 = 0 | (1 << 2) | (0 << 4);             // [hi|lo|hi]

    // 0) conversions + init
    {
        CvJobs cj;
        const float* srcs[9] = { x, W_ih_l0, W_ih_l0r, W_hh_l0, W_hh_l0r,
                                 W_hh_l1, W_ih_l1, W_ih_l1r, fc1_w };
        __nv_bfloat16* dsts[9] = { p_xs, p_ws + WS_IH_L0, p_ws + WS_IH_L0R,
                                   p_ws + WS_HH_L0, p_ws + WS_HH_L0R, p_ws + WS_HH_L1,
                                   p_ws + WS_IH_L1, p_ws + WS_IH_L1R, p_ws + WS_FC1 };
        int Ks[9]  = { 28, 28, 28, 512, 512, 512, 1024, 1024, 1024 };
        int Kps[9] = { 32, 32, 32, 512, 512, 512, 1024, 1024, 1024 };
        int mds[9] = { MODES_A4, MODES_W4, MODES_W4, MODES_W3, MODES_W3,
                       MODES_W3, MODES_W3, MODES_W3, MODES_W3 };
        int ils[9] = { 0, 1, 1, 1, 1, 1, 1, 0, 0 };
        int tots[9] = { MT * 128, 1536 * 128, 1536 * 128, 1536 * 1536, 1536 * 1536,
                        1536 * 1536, 1536 * 3072, 1536 * 3072, 256 * 3072 };
        int off = 0;
        for (int i = 0; i < 9; i++) {
            cj.src[i] = srcs[i]; cj.dst[i] = dsts[i];
            cj.K[i] = Ks[i]; cj.Kp[i] = Kps[i]; cj.modes[i] = mds[i];
            cj.total[i] = tots[i]; cj.ilv[i] = ils[i];
            cj.off[i] = off;
            off += (tots[i] + 255) / 256;
        }
        cj.off[9] = off;
        convert_all<<<off, 256>>>(cj);
        zero_all<<<(ZTOT + 255) / 256, 256>>>(b_ih_l0, b_ih_l0r, b_ih_l1);
    }

    // 1) layer-0 input projections (fwd+bwd), interleaved W + bias, K'=128
    {
        MOp f{ p_xs, p_xs, p_ws + WS_IH_L0,  p_bi,        p_gxA, 128, 0 };
        MOp r{ p_xs, p_xs, p_ws + WS_IH_L0R, p_bi + 1536, p_gxB, 128, 0 };
        mma_gemm<<<dim3(Gg / 128, MT / 128, 2), 256, SMEM_SZ>>>(f, r, 128, Gg, 128, 30);
    }

    // 2) layer-0 recurrence: gate-fused GEMM, fwd+bwd per launch
    for (int s = 0; s < Tt; s++) {
        const int cur = s & 1;
        const size_t ib = (size_t)cur * 2 * BH;
        const size_t ob = (size_t)(cur ^ 1) * 2 * BH;
        RStep f{ p_hh + ib,      p_hl + ib,      p_ws + WS_HH_L0,  b_hh_l0,  p_gxA,
                 p_h,      p_hh + ob,      p_hl + ob,      p_y0h, p_y0l, s, 0 };
        RStep r{ p_hh + ib + BH, p_hl + ib + BH, p_ws + WS_HH_L0R, b_hh_l0r, p_gxB,
                 p_h + BH, p_hh + ob + BH, p_hl + ob + BH, p_y0h, p_y0l, Tt - 1 - s, 512 };
        rec_step<<<dim3(16, Bv / 128, 2), 256, RS_SMEM>>>(f, r);
    }

    // 3) layer-1 input projection (fwd, all t), interleaved, K'=3072
    {
        MOp f{ p_y0h, p_y0l, p_ws + WS_IH_L1, p_bi + 3072, p_gxA, 1024, 0 };
        mma_gemm<<<dim3(Gg / 128, MT / 128, 1), 256, SMEM_SZ>>>(f, f, 3072, Gg, 3072, 10);
    }

    // 4) layer-1 bwd input projection at t=T-1 (natural layout path)
    {
        MOp f{ p_y0h + (size_t)(Tt - 1) * 1024, p_y0l + (size_t)(Tt - 1) * 1024,
               p_ws + WS_IH_L1R, b_ih_l1r, p_gx1b, Tt * 1024, 0 };
        mma_gemm<<<dim3(Gg / 128, Bv / 128, 1), 256, SMEM_SZ>>>(f, f, 3072, Gg, 3072, 10);
    }
    gate_l1b_last<<<BH / 256, 256>>>(b_hh_l1r);

    // 5) layer-1 fwd recurrence: gate-fused
    for (int s = 0; s < Tt; s++) {
        const int cur = s & 1;
        RStep f{ p_h1h + (size_t)cur * BH, p_h1l + (size_t)cur * BH,
                 p_ws + WS_HH_L1, b_hh_l1, p_gxA, p_h1,
                 p_h1h + (size_t)(cur ^ 1) * BH, p_h1l + (size_t)(cur ^ 1) * BH,
                 nullptr, nullptr, s, 0 };
        rec_step<<<dim3(16, Bv / 128, 1), 256, RS_SMEM>>>(f, f);
    }

    // 6) head
    concat_last<<<(Bv * H2) / 256, 256>>>();
    {
        MOp f{ p_lh, p_ll, p_ws + WS_FC1, fc1_b, p_z1, 1024, 0 };
        mma_gemm<<<dim3(256 / 128, Bv / 128, 1), 256, SMEM_SZ>>>(f, f, 3072, 256, 3072, 10);
    }
    head_kernel<<<Bv, 256>>>(bn_gamma, bn_beta, bn_mean, bn_var, fc2_w, fc2_b, out);
}

// round 14
// speedup vs baseline: 1.1025x; 1.1025x over previous
#include <cuda_runtime.h>
#include <cuda_bf16.h>
#include <math.h>
#include <stdint.h>

// Problem dims
#define Bv 4096
#define Tt 28
#define In 28
#define Hh 512
#define Gg 1536   // 3*H
#define H2 1024   // 2*H

#define BH 2097152      // B*H
#define BG 6291456      // B*3H
#define MT 114688       // B*T

// ---------------- scratch (static device allocations; allowed) ----------------
__device__ float g_gxA[176160768];   // B*T*3H : gx layer0 fwd, reused as gx layer1 fwd
__device__ float g_gxB[176160768];   // B*T*3H : gx layer0 bwd
__device__ float g_gh[2 * 6291456];  // L0: [dir][B,1536]; L1: [gh | gh2] split-K halves
__device__ float g_h[2 * 2097152];   // layer0 fwd/bwd hidden (fp32 state)
__device__ float g_h1[2097152];      // layer1 fwd hidden (fp32 state)
__device__ float g_h1b[2097152];     // layer1 bwd hidden (one step)
__device__ float g_gx1b[6291456];    // layer1 bwd gx at t=T-1
__device__ float g_z1[1048576];      // B*256 fc1 output
__device__ float g_zb[1536];         // zero bias

// bf16 operands. A-side stores hi+lo only; GEMMs synthesize [hi|hi|lo] virtually.
// W-side physically stacked [Wh|Wl|Wh].
__device__ __nv_bfloat16 g_xs[14680064];     // x stacked [B*T,128] physical [hi|hi|lo|0]
__device__ __nv_bfloat16 g_ws[17694720];     // weights arena (stacked)
__device__ __nv_bfloat16 g_y0h[117440512];   // y0 hi [B*T,1024]
__device__ __nv_bfloat16 g_y0l[117440512];   // y0 lo [B*T,1024]
__device__ __nv_bfloat16 g_hh[2*2*2097152];  // l0 h hi, [buf][dir][B,512]
__device__ __nv_bfloat16 g_hl[2*2*2097152];  // l0 h lo
__device__ __nv_bfloat16 g_h1h[2*2097152];   // l1 h hi, [buf][B,512]
__device__ __nv_bfloat16 g_h1l[2*2097152];   // l1 h lo
__device__ __nv_bfloat16 g_lasth[4194304];   // concat hi [B,1024]
__device__ __nv_bfloat16 g_lastl[4194304];   // concat lo [B,1024]

// Weight arena offsets (bf16 elements)
#define WS_IH_L0   0          // 1536 x 128
#define WS_IH_L0R  196608
#define WS_HH_L0   393216     // 1536 x 1536
#define WS_HH_L0R  2752512
#define WS_HH_L1   5111808
#define WS_IH_L1   7471104    // 1536 x 3072
#define WS_IH_L1R  12189696
#define WS_FC1     16908288   // 256 x 3072

// ============================================================================
// PTX helpers (baseline sm_80+ features; valid on .target sm_103)
// ============================================================================
__device__ __forceinline__ uint32_t smem_u32(const void* p) {
    uint32_t a;
    asm("{ .reg .u64 t; cvta.to.shared.u64 t, %1; cvt.u32.u64 %0, t; }" : "=r"(a) : "l"(p));
    return a;
}
__device__ __forceinline__ void cp16(uint32_t s, const void* g) {
    asm volatile("cp.async.cg.shared.global [%0], [%1], 16;" :: "r"(s), "l"(g));
}
__device__ __forceinline__ void ldsm4(uint32_t* r, uint32_t a) {
    asm volatile("ldmatrix.sync.aligned.m8n8.x4.shared.b16 {%0,%1,%2,%3}, [%4];"
                 : "=r"(r[0]), "=r"(r[1]), "=r"(r[2]), "=r"(r[3]) : "r"(a));
}
__device__ __forceinline__ void mma16816(float* d, const uint32_t* a, uint32_t b0, uint32_t b1) {
    asm volatile("mma.sync.aligned.m16n8k16.row.col.f32.bf16.bf16.f32 "
                 "{%0,%1,%2,%3}, {%4,%5,%6,%7}, {%8,%9}, {%0,%1,%2,%3};"
                 : "+f"(d[0]), "+f"(d[1]), "+f"(d[2]), "+f"(d[3])
                 : "r"(a[0]), "r"(a[1]), "r"(a[2]), "r"(a[3]), "r"(b0), "r"(b1));
}

__device__ __forceinline__ float sigmoidf_(float x) { return 1.f / (1.f + expf(-x)); }
__device__ __forceinline__ void split_bf16(float v, __nv_bfloat16& h, __nv_bfloat16& l) {
    h = __float2bfloat16(v);
    l = __float2bfloat16(v - __bfloat162float(h));
}

// ============================================================================
// Pipelined bf16 GEMM: C = A' @ W'^T + bias (fp32 accum), virtual-stacked A.
// A' column k maps to: seg = k>>kshift; seg<2 -> Ahi[k & mask], seg2 -> Alo.
// (physical A: kshift=30 so seg==0 always and k indexes Ahi directly)
// W: [N, ldw] physically stacked, offset by koff via pre-offset pointer.
// 128x128x64 CTA tiles, 3-stage cp.async, swizzled ldmatrix.
// 4 warps (2x2), warp tile 64x64 -> smem fragment traffic 64KB/chunk (was 96KB),
// raising the smem-crossbar-bound tensor ceiling from 67% toward 100%.
// ============================================================================
struct MOp {
    const __nv_bfloat16 *Ahi, *Alo;  // hi / lo A arrays (row stride lda each)
    const __nv_bfloat16 *W;          // stacked weights (pre-offset for split-K)
    const float *bias;
    float *C;
    int lda;
    int koff;                        // split-K offset into virtual A columns
};

#define STAGE_B 32768               // A tile 16KB + W tile 16KB
#define SMEM_SZ (3 * STAGE_B)       // 98304

__device__ __forceinline__ void prefetch_stage(const MOp& op, uint32_t sb, int c,
                                               int bm, int bn, int ldw,
                                               int kshift, int kmask, int tid)
{
    const int st = c % 3;
    const uint32_t abase = sb + st * STAGE_B;
    const uint32_t wbase = abase + 16384;
    const int kc0 = c * 64;
#pragma unroll
    for (int i = 0; i < 8; i++) {
        int v = tid + i * 128;          // 0..1023
        int row = v >> 3, ch = v & 7;   // 128 rows x 8 chunks(16B)
        int kg  = op.koff + kc0 + ch * 8;
        int seg = kg >> kshift;
        int off = kg & kmask;
        const __nv_bfloat16* g = (seg < 2 ? op.Ahi : op.Alo)
                               + (size_t)(bm + row) * op.lda + off;
        cp16(abase + row * 128 + ((ch ^ (row & 7)) << 4), g);
    }
#pragma unroll
    for (int i = 0; i < 8; i++) {
        int v = tid + i * 128;
        int row = v >> 3, ch = v & 7;
        const __nv_bfloat16* g = op.W + (size_t)(bn + row) * ldw + kc0 + ch * 8;
        cp16(wbase + row * 128 + ((ch ^ (row & 7)) << 4), g);
    }
    asm volatile("cp.async.commit_group;");
}

__global__ void __launch_bounds__(128, 2) mma_gemm(MOp op0, MOp op1,
                                                   int ldw, int ldc, int K, int kshift)
{
    extern __shared__ char smem[];
    MOp op = (blockIdx.z == 0) ? op0 : op1;
    const uint32_t sb = smem_u32(smem);
    const int kmask = (kshift >= 30) ? 0x3FFFFFFF : ((1 << kshift) - 1);
    const int tid  = threadIdx.x;
    const int wid  = tid >> 5;
    const int lane = tid & 31;
    const int bm = blockIdx.y * 128;
    const int bn = blockIdx.x * 128;
    const int wm = (wid >> 1) * 64;   // 2 warp rows
    const int wn = (wid & 1) * 64;    // 2 warp cols

    float acc[4][8][4];
#pragma unroll
    for (int i = 0; i < 4; i++)
#pragma unroll
        for (int j = 0; j < 8; j++)
#pragma unroll
            for (int r = 0; r < 4; r++) acc[i][j][r] = 0.f;

    const int nc = K >> 6;

    prefetch_stage(op, sb, 0, bm, bn, ldw, kshift, kmask, tid);
    if (nc > 1) prefetch_stage(op, sb, 1, bm, bn, ldw, kshift, kmask, tid);

    for (int c = 0; c < nc; c++) {
        if (c + 2 < nc) {
            prefetch_stage(op, sb, c + 2, bm, bn, ldw, kshift, kmask, tid);
            asm volatile("cp.async.wait_group 2;");
        } else if (c + 1 < nc) {
            asm volatile("cp.async.wait_group 1;");
        } else {
            asm volatile("cp.async.wait_group 0;");
        }
        __syncthreads();

        const int st = c % 3;
        const uint32_t abase = sb + st * STAGE_B;
        const uint32_t wbase = abase + 16384;

#pragma unroll
        for (int kk = 0; kk < 4; kk++) {   // K=16 steps within BK=64
            uint32_t a[4][4], b[4][4];
#pragma unroll
            for (int mf = 0; mf < 4; mf++) {
                int r   = wm + mf * 16 + ((lane >> 3) & 1) * 8 + (lane & 7);
                int cch = kk * 2 + (lane >> 4);
                ldsm4(a[mf], abase + r * 128 + ((cch ^ (r & 7)) << 4));
            }
#pragma unroll
            for (int nf = 0; nf < 4; nf++) {
                int r   = wn + nf * 16 + ((lane >> 4) & 1) * 8 + (lane & 7);
                int cch = kk * 2 + ((lane >> 3) & 1);
                ldsm4(b[nf], wbase + r * 128 + ((cch ^ (r & 7)) << 4));
            }
#pragma unroll
            for (int mf = 0; mf < 4; mf++)
#pragma unroll
                for (int nt = 0; nt < 8; nt++)
                    mma16816(acc[mf][nt], a[mf],
                             b[nt >> 1][(nt & 1) * 2], b[nt >> 1][(nt & 1) * 2 + 1]);
        }
        __syncthreads();
    }

    // epilogue: bias + fp32 store
#pragma unroll
    for (int mf = 0; mf < 4; mf++) {
        int row = bm + wm + mf * 16 + (lane >> 2);
#pragma unroll
        for (int nt = 0; nt < 8; nt++) {
            int col = bn + wn + nt * 8 + (lane & 3) * 2;
            float b0 = op.bias[col], b1 = op.bias[col + 1];
            float2 v0 = make_float2(acc[mf][nt][0] + b0, acc[mf][nt][1] + b1);
            float2 v1 = make_float2(acc[mf][nt][2] + b0, acc[mf][nt][3] + b1);
            *(float2*)(op.C + (size_t)row * ldc + col) = v0;
            *(float2*)(op.C + (size_t)(row + 8) * ldc + col) = v1;
        }
    }
}

// ============================================================================
// init: zero all state in one launch
// ============================================================================
#define ZF1 (2 * BH)
#define ZF2 (ZF1 + BH)
#define ZF3 (ZF2 + 1536)
#define ZB1 (2 * BH)
#define ZB2 (ZB1 + 2 * BH)
#define ZB3 (ZB2 + BH)
#define ZB4 (ZB3 + BH)
#define ZTOT (ZF3 + ZB4)

__global__ void zero_all(void)
{
    long long i = (long long)blockIdx.x * blockDim.x + threadIdx.x;
    if (i >= ZTOT) return;
    if (i < ZF3) {
        if (i < ZF1)      g_h[i] = 0.f;
        else if (i < ZF2) g_h1[i - ZF1] = 0.f;
        else              g_zb[i - ZF2] = 0.f;
    } else {
        long long k = i - ZF3;
        __nv_bfloat16 z = __float2bfloat16(0.f);
        if (k < ZB1)      g_hh[k] = z;
        else if (k < ZB2) g_hl[k - ZB1] = z;
        else if (k < ZB3) g_h1h[k - ZB2] = z;
        else              g_h1l[k - ZB3] = z;
    }
}

// ============================================================================
// conversion: all hi/lo stacking jobs in one launch (block-offset job table)
// per-seg mode: 0=hi, 1=lo, 2=zero
// ============================================================================
struct CvJobs {
    const float* src[9];
    __nv_bfloat16* dst[9];
    int off[10];          // cumulative block offsets
    int K[9], Kp[9], modes[9], total[9];
};

__global__ void convert_all(CvJobs jobs)
{
    int bid = blockIdx.x;
    int ji = 0;
#pragma unroll
    for (int t = 1; t < 9; t++) ji += (bid >= jobs.off[t]);
    int i = (bid - jobs.off[ji]) * 256 + threadIdx.x;
    if (i >= jobs.total[ji]) return;
    const float* src = jobs.src[ji];
    int K = jobs.K[ji], Kp = jobs.Kp[ji], modes = jobs.modes[ji];

    int Kt  = (Kp == 32) ? 128 : (Kp == 512 ? 1536 : 3072);
    int row = i / Kt;
    int rem = i - row * Kt;
    int seg = rem / Kp;
    int kk  = rem - seg * Kp;
    int mode = (modes >> (2 * seg)) & 3;
    float v = (mode != 2 && kk < K) ? src[(size_t)row * K + kk] : 0.f;
    __nv_bfloat16 h = __float2bfloat16(v);
    __nv_bfloat16 o = h;
    if (mode == 1) o = __float2bfloat16(v - __bfloat162float(h));
    jobs.dst[ji][i] = o;
}

// ============================================================================
// gate kernels
// ============================================================================
// Layer-0 gating, both directions (blockIdx.y = dir). fp32 state + hi/lo writes.
__global__ void gru_gate_l0(int s, int cur)
{
    const int idx = blockIdx.x * blockDim.x + threadIdx.x;  // over B*H
    const int dir = blockIdx.y;
    const int b = idx >> 9;
    const int j = idx & 511;
    const int t = (dir == 0) ? s : (Tt - 1 - s);

    const float* gx = (dir == 0 ? g_gxA : g_gxB) + ((size_t)b * Tt + t) * Gg;
    const float* gh = g_gh + (size_t)dir * BG + (size_t)b * Gg;
    const size_t hidx = (size_t)dir * BH + (size_t)b * Hh + j;

    float r = sigmoidf_(gx[j] + gh[j]);
    float z = sigmoidf_(gx[Hh + j] + gh[Hh + j]);
    float n = tanhf(gx[2 * Hh + j] + r * gh[2 * Hh + j]);
    float hn = (1.f - z) * n + z * g_h[hidx];
    g_h[hidx] = hn;

    __nv_bfloat16 hh, hl;
    split_bf16(hn, hh, hl);
    const size_t mo = (size_t)(cur ^ 1) * 2 * BH + hidx;
    g_hh[mo] = hh;  g_hl[mo] = hl;
    const size_t yi = ((size_t)b * Tt + t) * 1024 + (size_t)dir * Hh + j;
    g_y0h[yi] = hh; g_y0l[yi] = hl;
}

// Layer-1 gating: gh comes in two split-K halves summed here.
__global__ void gru_gate_l1(int s, int cur)
{
    const int idx = blockIdx.x * blockDim.x + threadIdx.x;
    const int b = idx >> 9;
    const int j = idx & 511;

    const float* gx  = g_gxA + ((size_t)b * Tt + s) * Gg;
    const float* gh  = g_gh + (size_t)b * Gg;
    const float* gh2 = g_gh + (size_t)BG + (size_t)b * Gg;
    const size_t hidx = (size_t)b * Hh + j;

    float ar = gh[j] + gh2[j];
    float az = gh[Hh + j] + gh2[Hh + j];
    float an = gh[2 * Hh + j] + gh2[2 * Hh + j];
    float r = sigmoidf_(gx[j] + ar);
    float z = sigmoidf_(gx[Hh + j] + az);
    float n = tanhf(gx[2 * Hh + j] + r * an);
    float hn = (1.f - z) * n + z * g_h1[hidx];
    g_h1[hidx] = hn;

    __nv_bfloat16 hh, hl;
    split_bf16(hn, hh, hl);
    const size_t mo = (size_t)(cur ^ 1) * BH + hidx;
    g_h1h[mo] = hh;  g_h1l[mo] = hl;
}

// Layer-1 backward: output at original t=T-1 is the FIRST reversed step (h0=0).
__global__ void gate_l1b_last(const float* __restrict__ bhh)
{
    const int idx = blockIdx.x * blockDim.x + threadIdx.x;
    const int b = idx >> 9;
    const int j = idx & 511;
    const float* gx = g_gx1b + (size_t)b * Gg;
    float r = sigmoidf_(gx[j] + bhh[j]);
    float z = sigmoidf_(gx[Hh + j] + bhh[Hh + j]);
    float n = tanhf(gx[2 * Hh + j] + r * bhh[2 * Hh + j]);
    g_h1b[(size_t)b * Hh + j] = (1.f - z) * n;
}

__global__ void concat_last(void)
{
    const int idx = blockIdx.x * blockDim.x + threadIdx.x;  // B*2H
    const int b = idx >> 10;
    const int j = idx & 1023;
    float v = (j < Hh) ? g_h1[(size_t)b * Hh + j] : g_h1b[(size_t)b * Hh + (j - Hh)];
    __nv_bfloat16 hh, hl;
    split_bf16(v, hh, hl);
    g_lasth[(size_t)b * H2 + j] = hh;
    g_lastl[(size_t)b * H2 + j] = hl;
}

// BN + ReLU + fc2 + log_softmax
__global__ void head_kernel(const float* __restrict__ gamma, const float* __restrict__ beta,
                            const float* __restrict__ mean, const float* __restrict__ var,
                            const float* __restrict__ fc2w, const float* __restrict__ fc2b,
                            float* __restrict__ out)
{
    const int b = blockIdx.x;
    const int tid = threadIdx.x;
    __shared__ float a[256];
    __shared__ float logits[10];

    float v = g_z1[(size_t)b * 256 + tid];
    v = (v - mean[tid]) * rsqrtf(var[tid] + 1e-5f) * gamma[tid] + beta[tid];
    a[tid] = fmaxf(v, 0.f);
    __syncthreads();

    if (tid < 10) {
        float acc = fc2b[tid];
        const float* wrow = fc2w + tid * 256;
        for (int k = 0; k < 256; k++) acc = fmaf(a[k], wrow[k], acc);
        logits[tid] = acc;
    }
    __syncthreads();

    if (tid == 0) {
        float mx = logits[0];
        for (int i = 1; i < 10; i++) mx = fmaxf(mx, logits[i]);
        float s = 0.f;
        for (int i = 0; i < 10; i++) s += expf(logits[i] - mx);
        float lse = mx + logf(s);
        for (int i = 0; i < 10; i++) out[(size_t)b * 10 + i] = logits[i] - lse;
    }
}

// ============================================================================
// host-side launch
// ============================================================================
extern "C" void kernel_launch(void* const* d_in, const int* in_sizes, int n_in,
                              void* d_out, int out_size)
{
    (void)in_sizes; (void)n_in; (void)out_size;
    const float* x         = (const float*)d_in[0];
    const float* W_ih_l0   = (const float*)d_in[1];
    const float* W_hh_l0   = (const float*)d_in[2];
    const float* b_ih_l0   = (const float*)d_in[3];
    const float* b_hh_l0   = (const float*)d_in[4];
    const float* W_ih_l0r  = (const float*)d_in[5];
    const float* W_hh_l0r  = (const float*)d_in[6];
    const float* b_ih_l0r  = (const float*)d_in[7];
    const float* b_hh_l0r  = (const float*)d_in[8];
    const float* W_ih_l1   = (const float*)d_in[9];
    const float* W_hh_l1   = (const float*)d_in[10];
    const float* b_ih_l1   = (const float*)d_in[11];
    const float* b_hh_l1   = (const float*)d_in[12];
    const float* W_ih_l1r  = (const float*)d_in[13];
    const float* W_hh_l1r  = (const float*)d_in[14];
    const float* b_ih_l1r  = (const float*)d_in[15];
    const float* b_hh_l1r  = (const float*)d_in[16];
    const float* fc1_w     = (const float*)d_in[17];
    const float* fc1_b     = (const float*)d_in[18];
    const float* bn_gamma  = (const float*)d_in[19];
    const float* bn_beta   = (const float*)d_in[20];
    const float* bn_mean   = (const float*)d_in[21];
    const float* bn_var    = (const float*)d_in[22];
    const float* fc2_w     = (const float*)d_in[23];
    const float* fc2_b     = (const float*)d_in[24];
    float* out = (float*)d_out;

    float *p_gxA, *p_gxB, *p_gh, *p_gx1b, *p_z1, *p_zb;
    __nv_bfloat16 *p_xs, *p_ws, *p_y0h, *p_y0l, *p_hh, *p_hl, *p_h1h, *p_h1l, *p_lh, *p_ll;
    cudaGetSymbolAddress((void**)&p_gxA,  g_gxA);
    cudaGetSymbolAddress((void**)&p_gxB,  g_gxB);
    cudaGetSymbolAddress((void**)&p_gh,   g_gh);
    cudaGetSymbolAddress((void**)&p_gx1b, g_gx1b);
    cudaGetSymbolAddress((void**)&p_z1,   g_z1);
    cudaGetSymbolAddress((void**)&p_zb,   g_zb);
    cudaGetSymbolAddress((void**)&p_xs,   g_xs);
    cudaGetSymbolAddress((void**)&p_ws,   g_ws);
    cudaGetSymbolAddress((void**)&p_y0h,  g_y0h);
    cudaGetSymbolAddress((void**)&p_y0l,  g_y0l);
    cudaGetSymbolAddress((void**)&p_hh,   g_hh);
    cudaGetSymbolAddress((void**)&p_hl,   g_hl);
    cudaGetSymbolAddress((void**)&p_h1h,  g_h1h);
    cudaGetSymbolAddress((void**)&p_h1l,  g_h1l);
    cudaGetSymbolAddress((void**)&p_lh,   g_lasth);
    cudaGetSymbolAddress((void**)&p_ll,   g_lastl);

    cudaFuncSetAttribute(mma_gemm, cudaFuncAttributeMaxDynamicSharedMemorySize, SMEM_SZ);

    // seg-mode packs: 0=hi, 1=lo, 2=zero (2 bits per segment)
    const int MODES_A4 = 0 | (0 << 2) | (1 << 4) | (2 << 6);  // [hi|hi|lo|0]
    const int MODES_W4 = 0 | (1 << 2) | (0 << 4) | (2 << 6);  // [hi|lo|hi|0]
    const int MODES_W3 = 0 | (1 << 2) | (0 << 4);             // [hi|lo|hi]

    // 0) conversions (one launch) + zero init (one launch)
    {
        CvJobs cj;
        const float* srcs[9] = { x, W_ih_l0, W_ih_l0r, W_hh_l0, W_hh_l0r,
                                 W_hh_l1, W_ih_l1, W_ih_l1r, fc1_w };
        __nv_bfloat16* dsts[9] = { p_xs, p_ws + WS_IH_L0, p_ws + WS_IH_L0R,
                                   p_ws + WS_HH_L0, p_ws + WS_HH_L0R, p_ws + WS_HH_L1,
                                   p_ws + WS_IH_L1, p_ws + WS_IH_L1R, p_ws + WS_FC1 };
        int Ks[9]  = { 28, 28, 28, 512, 512, 512, 1024, 1024, 1024 };
        int Kps[9] = { 32, 32, 32, 512, 512, 512, 1024, 1024, 1024 };
        int mds[9] = { MODES_A4, MODES_W4, MODES_W4, MODES_W3, MODES_W3,
                       MODES_W3, MODES_W3, MODES_W3, MODES_W3 };
        int tots[9] = { MT * 128, 1536 * 128, 1536 * 128, 1536 * 1536, 1536 * 1536,
                        1536 * 1536, 1536 * 3072, 1536 * 3072, 256 * 3072 };
        int off = 0;
        for (int i = 0; i < 9; i++) {
            cj.src[i] = srcs[i]; cj.dst[i] = dsts[i];
            cj.K[i] = Ks[i]; cj.Kp[i] = Kps[i]; cj.modes[i] = mds[i]; cj.total[i] = tots[i];
            cj.off[i] = off;
            off += (tots[i] + 255) / 256;
        }
        cj.off[9] = off;
        convert_all<<<off, 256>>>(cj);
        zero_all<<<(ZTOT + 255) / 256, 256>>>();
    }

    // 1) layer-0 input projections (fwd+bwd), physical stacked xs, K'=128
    {
        MOp f{ p_xs, p_xs, p_ws + WS_IH_L0,  b_ih_l0,  p_gxA, 128, 0 };
        MOp r{ p_xs, p_xs, p_ws + WS_IH_L0R, b_ih_l0r, p_gxB, 128, 0 };
        mma_gemm<<<dim3(Gg / 128, MT / 128, 2), 128, SMEM_SZ>>>(f, r, 128, Gg, 128, 30);
    }

    // 2) layer-0 recurrence: GEMM (virtual [hi|hi|lo], K'=1536) + gate, per step
    for (int s = 0; s < Tt; s++) {
        const int cur = s & 1;
        const size_t mb = (size_t)cur * 2 * BH;
        MOp f{ p_hh + mb,      p_hl + mb,      p_ws + WS_HH_L0,  b_hh_l0,  p_gh,      512, 0 };
        MOp r{ p_hh + mb + BH, p_hl + mb + BH, p_ws + WS_HH_L0R, b_hh_l0r, p_gh + BG, 512, 0 };
        mma_gemm<<<dim3(Gg / 128, Bv / 128, 2), 128, SMEM_SZ>>>(f, r, Gg, Gg, Gg, 9);
        gru_gate_l0<<<dim3(BH / 256, 2), 256>>>(s, cur);
    }

    // 3) layer-1 input projection (fwd, all t), virtual y0 [hi|hi|lo], K'=3072
    {
        MOp f{ p_y0h, p_y0l, p_ws + WS_IH_L1, b_ih_l1, p_gxA, 1024, 0 };
        mma_gemm<<<dim3(Gg / 128, MT / 128, 1), 128, SMEM_SZ>>>(f, f, 3072, Gg, 3072, 10);
    }

    // 4) layer-1 bwd input projection at t=T-1 only
    {
        MOp f{ p_y0h + (size_t)(Tt - 1) * 1024, p_y0l + (size_t)(Tt - 1) * 1024,
               p_ws + WS_IH_L1R, b_ih_l1r, p_gx1b, Tt * 1024, 0 };
        mma_gemm<<<dim3(Gg / 128, Bv / 128, 1), 128, SMEM_SZ>>>(f, f, 3072, Gg, 3072, 10);
    }
    gate_l1b_last<<<BH / 256, 256>>>(b_hh_l1r);

    // 5) layer-1 fwd recurrence: split-K (two 768-halves) to fix wave quantization
    for (int s = 0; s < Tt; s++) {
        const int cur = s & 1;
        const size_t mb = (size_t)cur * BH;
        MOp h0{ p_h1h + mb, p_h1l + mb, p_ws + WS_HH_L1,       b_hh_l1, p_gh,      512, 0 };
        MOp h1{ p_h1h + mb, p_h1l + mb, p_ws + WS_HH_L1 + 768, p_zb,    p_gh + BG, 512, 768 };
        mma_gemm<<<dim3(Gg / 128, Bv / 128, 2), 128, SMEM_SZ>>>(h0, h1, Gg, Gg, 768, 9);
        gru_gate_l1<<<BH / 256, 256>>>(s, cur);
    }

    // 6) head
    concat_last<<<(Bv * H2) / 256, 256>>>();
    {
        MOp f{ p_lh, p_ll, p_ws + WS_FC1, fc1_b, p_z1, 1024, 0 };
        mma_gemm<<<dim3(256 / 128, Bv / 128, 1), 128, SMEM_SZ>>>(f, f, 3072, 256, 3072, 10);
    }
    head_kernel<<<Bv, 256>>>(bn_gamma, bn_beta, bn_mean, bn_var, fc2_w, fc2_b, out);
}